// round 7
// baseline (speedup 1.0000x reference)
#include <cuda_runtime.h>
#include <cuda_bf16.h>
#include <cstdint>
#include <cstddef>

#define B_   8
#define T_   2048
#define D_   1024
#define H_   4
#define HS_  256
#define U_   1365
#define U2_  2730
#define U2P  2816
#define UPAD 1408
#define BT_  (B_ * T_)
#define EPSV 1e-5f

#if defined(__CUDA_ARCH_FEAT_SM103_ALL) || defined(__CUDA_ARCH_FEAT_SM100_ALL)
#define HAS_TC 1
#else
#define HAS_TC 0
#endif

// ---------------- scratch ----------------
__device__ float g_xn[(size_t)BT_ * D_];
__device__ float g_iflin[(size_t)BT_ * 2048];
__device__ float g_zolin[(size_t)BT_ * 2048];
__device__ float g_up[(size_t)BT_ * U2P];
__device__ float g_whhT[H_ * HS_ * 1024];
__device__ float g_upb[U2P];

__device__ __nv_bfloat16 g_xn_h[(size_t)BT_ * D_];
__device__ __nv_bfloat16 g_xn_l[(size_t)BT_ * D_];
__device__ __nv_bfloat16 g_if_h[(size_t)BT_ * D_];
__device__ __nv_bfloat16 g_if_l[(size_t)BT_ * D_];
__device__ __nv_bfloat16 g_zn_h[(size_t)BT_ * D_];
__device__ __nv_bfloat16 g_zn_l[(size_t)BT_ * D_];
__device__ __nv_bfloat16 g_act_h[(size_t)BT_ * UPAD];
__device__ __nv_bfloat16 g_act_l[(size_t)BT_ * UPAD];
__device__ __nv_bfloat16 g_wif_h[2048 * 1024];
__device__ __nv_bfloat16 g_wif_l[2048 * 1024];
__device__ __nv_bfloat16 g_wzo_h[2048 * 1024];
__device__ __nv_bfloat16 g_wzo_l[2048 * 1024];
__device__ __nv_bfloat16 g_wup_h[(size_t)U2P * 1024];
__device__ __nv_bfloat16 g_wup_l[(size_t)U2P * 1024];
__device__ __nv_bfloat16 g_wdn_h[1024 * UPAD];
__device__ __nv_bfloat16 g_wdn_l[1024 * UPAD];

__device__ __forceinline__ void split2(float v, __nv_bfloat16& h, __nv_bfloat16& l) {
    h = __float2bfloat16(v);
    l = __float2bfloat16(v - __bfloat162float(h));
}

// ---------------- LayerNorm: fp32 out + bf16 split ----------------
__global__ void __launch_bounds__(256) ln_kernel(const float* __restrict__ x,
                                                 const float* __restrict__ ln_w,
                                                 const float* __restrict__ ln_b) {
    __shared__ float sred[18];
    const int bt = blockIdx.x, tid = threadIdx.x;
    const float4 xv = reinterpret_cast<const float4*>(x + (size_t)bt * D_)[tid];
    float s = xv.x + xv.y + xv.z + xv.w;
    float q = xv.x * xv.x + xv.y * xv.y + xv.z * xv.z + xv.w * xv.w;
#pragma unroll
    for (int off = 16; off; off >>= 1) {
        s += __shfl_xor_sync(0xffffffffu, s, off);
        q += __shfl_xor_sync(0xffffffffu, q, off);
    }
    if ((tid & 31) == 0) { sred[tid >> 5] = s; sred[8 + (tid >> 5)] = q; }
    __syncthreads();
    if (tid == 0) {
        float ts = 0.f, tq = 0.f;
#pragma unroll
        for (int i = 0; i < 8; i++) { ts += sred[i]; tq += sred[8 + i]; }
        sred[16] = ts; sred[17] = tq;
    }
    __syncthreads();
    const float mean = sred[16] * (1.f / D_);
    const float var  = sred[17] * (1.f / D_) - mean * mean;
    const float inv  = rsqrtf(var + EPSV);
    const float4 wv = reinterpret_cast<const float4*>(ln_w)[tid];
    const float4 bv = reinterpret_cast<const float4*>(ln_b)[tid];
    float4 r;
    r.x = (xv.x - mean) * inv * wv.x + bv.x;
    r.y = (xv.y - mean) * inv * wv.y + bv.y;
    r.z = (xv.z - mean) * inv * wv.z + bv.z;
    r.w = (xv.w - mean) * inv * wv.w + bv.w;
    reinterpret_cast<float4*>(g_xn + (size_t)bt * D_)[tid] = r;
    const size_t o = (size_t)bt * D_ + tid * 4;
    split2(r.x, g_xn_h[o + 0], g_xn_l[o + 0]);
    split2(r.y, g_xn_h[o + 1], g_xn_l[o + 1]);
    split2(r.z, g_xn_h[o + 2], g_xn_l[o + 2]);
    split2(r.w, g_xn_h[o + 3], g_xn_l[o + 3]);
}

// ---------------- causal conv K=4 + swish: bf16 split only ----------------
__global__ void __launch_bounds__(256) conv_swish_kernel(const float* __restrict__ conv_w,
                                                         const float* __restrict__ conv_b) {
    const int bt = blockIdx.x;
    const int b = bt / T_, t = bt % T_;
    const int tid = threadIdx.x, c0 = tid * 4;
    float4 acc = reinterpret_cast<const float4*>(conv_b)[tid];
    const float4 w0 = reinterpret_cast<const float4*>(conv_w)[c0 + 0];
    const float4 w1 = reinterpret_cast<const float4*>(conv_w)[c0 + 1];
    const float4 w2 = reinterpret_cast<const float4*>(conv_w)[c0 + 2];
    const float4 w3 = reinterpret_cast<const float4*>(conv_w)[c0 + 3];
#pragma unroll
    for (int k = 0; k < 4; k++) {
        const int tt = t - 3 + k;
        if (tt >= 0) {
            const float4 xv =
                reinterpret_cast<const float4*>(g_xn + (size_t)(b * T_ + tt) * D_)[tid];
            acc.x += ((const float*)&w0)[k] * xv.x;
            acc.y += ((const float*)&w1)[k] * xv.y;
            acc.z += ((const float*)&w2)[k] * xv.z;
            acc.w += ((const float*)&w3)[k] * xv.w;
        }
    }
    const size_t o = (size_t)bt * D_ + c0;
    float vx = acc.x / (1.f + expf(-acc.x));
    float vy = acc.y / (1.f + expf(-acc.y));
    float vz = acc.z / (1.f + expf(-acc.z));
    float vw = acc.w / (1.f + expf(-acc.w));
    split2(vx, g_if_h[o + 0], g_if_l[o + 0]);
    split2(vy, g_if_h[o + 1], g_if_l[o + 1]);
    split2(vz, g_if_h[o + 2], g_if_l[o + 2]);
    split2(vw, g_if_h[o + 3], g_if_l[o + 3]);
}

// ---------------- weight_hh [H][1024][256] -> [H][256][1024] ----------------
__global__ void transpose_whh(const float* __restrict__ whh) {
    __shared__ float tile[32][33];
    const int h = blockIdx.z;
    const int o0 = blockIdx.x * 32, s0 = blockIdx.y * 32;
    const int tx = threadIdx.x, ty = threadIdx.y;
    for (int i = ty; i < 32; i += 8)
        tile[i][tx] = whh[((size_t)h * 1024 + o0 + i) * 256 + s0 + tx];
    __syncthreads();
    for (int i = ty; i < 32; i += 8)
        g_whhT[((size_t)h * 256 + s0 + i) * 1024 + o0 + tx] = tile[tx][i];
}

// ---------------- weight preprocessing ----------------
__global__ void split_kernel(const float* __restrict__ src, __nv_bfloat16* __restrict__ h,
                             __nv_bfloat16* __restrict__ l, int n) {
    for (int i = blockIdx.x * 256 + threadIdx.x; i < n; i += gridDim.x * 256)
        split2(src[i], h[i], l[i]);
}

__global__ void __launch_bounds__(256) pad_split_upw(const float* __restrict__ w) {
    const int n = blockIdx.x;
    for (int j = threadIdx.x; j < 1024; j += 256) {
        float v = (n < U2_) ? w[(size_t)n * 1024 + j] : 0.f;
        split2(v, g_wup_h[(size_t)n * 1024 + j], g_wup_l[(size_t)n * 1024 + j]);
    }
}

__global__ void pad_upb_kernel(const float* __restrict__ b) {
    const int i = blockIdx.x * 256 + threadIdx.x;
    if (i < U2P) g_upb[i] = (i < U2_) ? b[i] : 0.f;
}

__global__ void __launch_bounds__(256) pad_split_downw(const float* __restrict__ dw) {
    const int n = blockIdx.x;
    for (int j = threadIdx.x; j < UPAD; j += 256) {
        float v = (j < U_) ? dw[(size_t)n * U_ + j] : 0.f;
        split2(v, g_wdn_h[(size_t)n * UPAD + j], g_wdn_l[(size_t)n * UPAD + j]);
    }
}

// ================= tcgen05 GEMM =================
#define STG_BYTES 98304
#define TILES0    1024
#define IDESC ((1u << 4) | (1u << 7) | (1u << 10) | (32u << 17) | (8u << 24))
#define DESC_BASE ((2ull << 61) | (1ull << 46) | (64ull << 32) | (1ull << 16))

#if HAS_TC
static __device__ __forceinline__ uint32_t sw128(uint32_t off) {
    return off ^ ((off >> 3) & 0x70);
}
static __device__ __forceinline__ void cpa16(uint32_t dst, const void* src) {
    asm volatile("cp.async.cg.shared.global [%0], [%1], 16;" :: "r"(dst), "l"(src));
}
static __device__ __forceinline__ void mma_f16_ss(uint32_t d, uint64_t a, uint64_t b,
                                                  uint32_t en) {
    asm volatile(
        "{\n\t.reg .pred p;\n\t"
        "setp.ne.u32 p, %5, 0;\n\t"
        "tcgen05.mma.cta_group::1.kind::f16 [%0], %1, %2, %3, {%4,%4,%4,%4}, p;\n\t}"
        :: "r"(d), "l"(a), "l"(b), "r"(IDESC), "r"(0u), "r"(en) : "memory");
}
static __device__ __forceinline__ void mwait(uint32_t mbar, uint32_t parity) {
    asm volatile(
        "{\n\t.reg .pred P;\n\t"
        "LW%=:\n\t"
        "mbarrier.try_wait.parity.shared.b64 P, [%0], %1;\n\t"
        "@!P bra LW%=;\n\t}"
        :: "r"(mbar), "r"(parity) : "memory");
}
static __device__ __forceinline__ void load_stage_tc(uint32_t sb, int s, int tid,
    const __nv_bfloat16* Ah, const __nv_bfloat16* Al, int lda, int m0,
    const __nv_bfloat16* Bh, const __nv_bfloat16* Bl, int ldb, int n0, int k0) {
    const uint32_t st = sb + TILES0 + s * STG_BYTES;
#pragma unroll
    for (int j = 0; j < 8; j++) {
        const int i = tid + j * 128;
        const int row = i >> 3, c16 = i & 7;
        const uint32_t sw = sw128(row * 128 + c16 * 16);
        const size_t go = (size_t)(m0 + row) * lda + k0 + c16 * 8;
        cpa16(st + sw,         Ah + go);
        cpa16(st + 16384 + sw, Al + go);
    }
#pragma unroll
    for (int j = 0; j < 16; j++) {
        const int i = tid + j * 128;
        const int row = i >> 3, c16 = i & 7;
        const uint32_t sw = sw128(row * 128 + c16 * 16);
        const size_t go = (size_t)(n0 + row) * ldb + k0 + c16 * 8;
        cpa16(st + 32768 + sw, Bh + go);
        cpa16(st + 65536 + sw, Bl + go);
    }
    asm volatile("cp.async.commit_group;");
}
#endif

__global__ void __launch_bounds__(128) gemm_tc(
    const __nv_bfloat16* __restrict__ Ah, const __nv_bfloat16* __restrict__ Al, int lda,
    const __nv_bfloat16* __restrict__ Bh, const __nv_bfloat16* __restrict__ Bl, int ldb,
    float* __restrict__ C, int ldc, int K,
    const float* __restrict__ bias, const float* __restrict__ res) {
#if HAS_TC
    extern __shared__ char smem[];
    const uint32_t sb = (uint32_t)__cvta_generic_to_shared(smem);
    const int tid = threadIdx.x;
    const int m0 = blockIdx.y * 128, n0 = blockIdx.x * 256;
    const int iters = K >> 6;

    if (tid < 32) {
        asm volatile("tcgen05.alloc.cta_group::1.sync.aligned.shared::cta.b32 [%0], %1;"
                     :: "r"(sb), "r"(256u) : "memory");
        asm volatile("tcgen05.relinquish_alloc_permit.cta_group::1.sync.aligned;");
    }
    if (tid == 0) {
        asm volatile("mbarrier.init.shared.b64 [%0], 1;" :: "r"(sb + 8)  : "memory");
        asm volatile("mbarrier.init.shared.b64 [%0], 1;" :: "r"(sb + 16) : "memory");
    }
    __syncthreads();
    uint32_t tmem;
    asm volatile("ld.shared.b32 %0, [%1];" : "=r"(tmem) : "r"(sb));

    int pp[2] = {0, 0};
    load_stage_tc(sb, 0, tid, Ah, Al, lda, m0, Bh, Bl, ldb, n0, 0);

    for (int it = 0; it < iters; it++) {
        const int s = it & 1;
        if (it + 1 < iters) {
            const int o = s ^ 1;
            if (it >= 1) { mwait(sb + 8 + o * 8, pp[o]); pp[o] ^= 1; }
            load_stage_tc(sb, o, tid, Ah, Al, lda, m0, Bh, Bl, ldb, n0, (it + 1) * 64);
            asm volatile("cp.async.wait_group 1;");
        } else {
            asm volatile("cp.async.wait_group 0;");
        }
        asm volatile("fence.proxy.async.shared::cta;" ::: "memory");
        __syncthreads();
        if (tid == 0) {
            const uint32_t st = sb + TILES0 + s * STG_BYTES;
            const uint64_t ah = DESC_BASE | ((uint64_t)(st >> 4) & 0x3FFF);
            const uint64_t al = DESC_BASE | ((uint64_t)((st + 16384) >> 4) & 0x3FFF);
            const uint64_t bh = DESC_BASE | ((uint64_t)((st + 32768) >> 4) & 0x3FFF);
            const uint64_t bl = DESC_BASE | ((uint64_t)((st + 65536) >> 4) & 0x3FFF);
#pragma unroll
            for (int ks = 0; ks < 4; ks++) {
                mma_f16_ss(tmem, ah + ks * 2, bh + ks * 2, (it > 0 || ks > 0) ? 1u : 0u);
                mma_f16_ss(tmem, ah + ks * 2, bl + ks * 2, 1u);
                mma_f16_ss(tmem, al + ks * 2, bh + ks * 2, 1u);
            }
            asm volatile(
                "tcgen05.commit.cta_group::1.mbarrier::arrive::one.shared::cluster.b64 [%0];"
                :: "r"(sb + 8 + s * 8) : "memory");
        }
    }
    const int sl = (iters - 1) & 1;
    mwait(sb + 8 + sl * 8, pp[sl]);
    asm volatile("tcgen05.fence::after_thread_sync;" ::: "memory");
    __syncthreads();

    const int wid = tid >> 5, lid = tid & 31;
    const int row = m0 + wid * 32 + lid;
    float* crow = C + (size_t)row * ldc;
    const float* rrow = res ? res + (size_t)row * ldc : nullptr;
    for (int cb = 0; cb < 8; cb++) {
        uint32_t r[32];
        asm volatile(
            "tcgen05.ld.sync.aligned.32x32b.x32.b32 "
            "{%0,%1,%2,%3,%4,%5,%6,%7,%8,%9,%10,%11,%12,%13,%14,%15,"
            "%16,%17,%18,%19,%20,%21,%22,%23,%24,%25,%26,%27,%28,%29,%30,%31}, [%32];"
            : "=r"(r[0]), "=r"(r[1]), "=r"(r[2]), "=r"(r[3]), "=r"(r[4]), "=r"(r[5]),
              "=r"(r[6]), "=r"(r[7]), "=r"(r[8]), "=r"(r[9]), "=r"(r[10]), "=r"(r[11]),
              "=r"(r[12]), "=r"(r[13]), "=r"(r[14]), "=r"(r[15]), "=r"(r[16]), "=r"(r[17]),
              "=r"(r[18]), "=r"(r[19]), "=r"(r[20]), "=r"(r[21]), "=r"(r[22]), "=r"(r[23]),
              "=r"(r[24]), "=r"(r[25]), "=r"(r[26]), "=r"(r[27]), "=r"(r[28]), "=r"(r[29]),
              "=r"(r[30]), "=r"(r[31])
            : "r"(tmem + cb * 32));
        asm volatile("tcgen05.wait::ld.sync.aligned;" ::: "memory");
        const int c0 = n0 + cb * 32;
#pragma unroll
        for (int j = 0; j < 32; j += 4) {
            float4 v = make_float4(__uint_as_float(r[j]), __uint_as_float(r[j + 1]),
                                   __uint_as_float(r[j + 2]), __uint_as_float(r[j + 3]));
            if (bias) {
                v.x += bias[c0 + j];     v.y += bias[c0 + j + 1];
                v.z += bias[c0 + j + 2]; v.w += bias[c0 + j + 3];
            }
            if (rrow) {
                v.x += rrow[c0 + j];     v.y += rrow[c0 + j + 1];
                v.z += rrow[c0 + j + 2]; v.w += rrow[c0 + j + 3];
            }
            *reinterpret_cast<float4*>(crow + c0 + j) = v;
        }
    }
    __syncthreads();
    if (tid < 32)
        asm volatile("tcgen05.dealloc.cta_group::1.sync.aligned.b32 %0, %1;"
                     :: "r"(tmem), "r"(256u));
#endif
}

// ============ recurrence: 8-CTA cluster per (head, batch-pair) ============
static __device__ __forceinline__ uint32_t smem_u32(const void* p) {
    return (uint32_t)__cvta_generic_to_shared(p);
}
static __device__ __forceinline__ void dsmem_st_f32(uint32_t laddr, uint32_t rank, float v) {
    uint32_t ra;
    asm volatile("mapa.shared::cluster.u32 %0, %1, %2;" : "=r"(ra) : "r"(laddr), "r"(rank));
    asm volatile("st.shared::cluster.b32 [%0], %1;" :: "r"(ra), "r"(__float_as_uint(v)));
}
static __device__ __forceinline__ void csync() {
    asm volatile("barrier.cluster.arrive.aligned;" ::: "memory");
    asm volatile("barrier.cluster.wait.aligned;" ::: "memory");
}

__global__ void __launch_bounds__(128) __cluster_dims__(8, 1, 1)
recurrence_cluster(const float* __restrict__ bias,
                   const float* __restrict__ gn_w,
                   const float* __restrict__ gn_b) {
    extern __shared__ float sm[];
    float* sW   = sm;                 // pairs: [i<128][tid<128][2]
    float* sH   = sm + 32768;         // [2][256][2]
    float* sPre = sH + 1024;          // [2][128]
    float* sRed = sPre + 256;         // 16

    const int tid = threadIdx.x;
    uint32_t rank;
    asm("mov.u32 %0, %%cluster_ctarank;" : "=r"(rank));
    const int cid = blockIdx.x >> 3;
    const int h = cid & 3, bp = cid >> 2;
    const int b0 = bp * 2, b1 = b0 + 1;
    const int g = tid >> 5, sl = tid & 31;
    const int sglob = (int)rank * 32 + sl;
    const int orow = g * 256 + sglob;

    // interleaved pair layout: sW[(s>>1)*256 + tid*2 + (s&1)]
    for (int s = 0; s < 256; s++)
        sW[(s >> 1) * 256 + tid * 2 + (s & 1)] =
            g_whhT[((size_t)(h * 256 + s)) * 1024 + orow];
    for (int i = tid; i < 1024; i += 128) sH[i] = 0.f;

    const float bia = bias[h * 1024 + orow];
    const float* linp; int lcol;
    if (g < 2) { linp = g_iflin; lcol = h * 512 + g * 256 + sglob; }
    else       { linp = g_zolin; lcol = h * 512 + (g - 2) * 256 + sglob; }
    const int s_out = (int)rank * 32 + (tid & 31);
    const float gwv = gn_w[h * 256 + s_out];
    const float gbv = gn_b[h * 256 + s_out];

    float cS = 0.f, nS = 0.f, mS = 0.f;
    __syncthreads();
    csync();

    const uint32_t sH_addr = smem_u32(sH);

    for (int t = 0; t < T_; t++) {
        const int cur = t & 1, nxt = cur ^ 1;
        const float lp0 = linp[(size_t)(b0 * T_ + t) * 2048 + lcol];
        const float lp1 = linp[(size_t)(b1 * T_ + t) * 2048 + lcol];

        float a0 = 0.f, a1 = 0.f;
        const float2* wp = reinterpret_cast<const float2*>(sW);
        const float4* hp = reinterpret_cast<const float4*>(sH + cur * 512);
#pragma unroll 8
        for (int i = 0; i < 128; i++) {
            const float2 w  = wp[i * 128 + tid];
            const float4 hh = hp[i];
            a0 += w.x * hh.x + w.y * hh.z;
            a1 += w.x * hh.y + w.y * hh.w;
        }
        sPre[tid]       = a0 + lp0 + bia;
        sPre[128 + tid] = a1 + lp1 + bia;
        __syncthreads();

        if (tid < 64) {
            const int bsel = tid >> 5, lane = tid & 31;
            const float* pr = sPre + bsel * 128;
            const float iv = pr[lane];
            const float fv = pr[32 + lane];
            const float zv = tanhf(pr[64 + lane]);
            const float og = 1.f / (1.f + expf(-pr[96 + lane]));
            const float mn = fmaxf(fv + mS, iv);
            const float ie = expf(iv - mn);
            const float fe = expf(fv + mS - mn);
            cS = fe * cS + ie * zv;
            nS = fe * nS + ie;
            mS = mn;
            const float hv = og * (cS / nS);
            const int soff = (nxt * 256 + s_out) * 2 + bsel;
            const uint32_t la = sH_addr + soff * 4;
#pragma unroll
            for (int p = 0; p < 8; p++) dsmem_st_f32(la, (uint32_t)p, hv);
        }
        csync();

        const float* hn = sH + nxt * 512;
        const float x0a = hn[tid * 2],         x1a = hn[tid * 2 + 1];
        const float x0b = hn[(tid + 128) * 2], x1b = hn[(tid + 128) * 2 + 1];
        float s0 = x0a + x0b, q0 = x0a * x0a + x0b * x0b;
        float s1 = x1a + x1b, q1 = x1a * x1a + x1b * x1b;
#pragma unroll
        for (int off = 16; off; off >>= 1) {
            s0 += __shfl_xor_sync(0xffffffffu, s0, off);
            q0 += __shfl_xor_sync(0xffffffffu, q0, off);
            s1 += __shfl_xor_sync(0xffffffffu, s1, off);
            q1 += __shfl_xor_sync(0xffffffffu, q1, off);
        }
        if ((tid & 31) == 0) {
            const int w = tid >> 5;
            sRed[w] = s0; sRed[4 + w] = q0; sRed[8 + w] = s1; sRed[12 + w] = q1;
        }
        __syncthreads();
        if (tid < 64) {
            const int bsel = tid >> 5;
            const float ts = (bsel ? (sRed[8] + sRed[9] + sRed[10] + sRed[11])
                                   : (sRed[0] + sRed[1] + sRed[2] + sRed[3]));
            const float tq = (bsel ? (sRed[12] + sRed[13] + sRed[14] + sRed[15])
                                   : (sRed[4] + sRed[5] + sRed[6] + sRed[7]));
            const float mu  = ts * (1.f / 256.f);
            const float var = tq * (1.f / 256.f) - mu * mu;
            const float inv = rsqrtf(var + EPSV);
            const float hval = hn[s_out * 2 + bsel];
            const float zn = (hval - mu) * inv * gwv + gbv;
            const int bb = bsel ? b1 : b0;
            const size_t zo = (size_t)(bb * T_ + t) * D_ + h * 256 + s_out;
            split2(zn, g_zn_h[zo], g_zn_l[zo]);
        }
        __syncthreads();
    }
}

// ---------------- GLU: act = gelu_tanh(u1)*u2, bf16 split ----------------
__global__ void __launch_bounds__(256) glu_kernel() {
    const int bt = blockIdx.x;
    const float* up = g_up + (size_t)bt * U2P;
    for (int j = threadIdx.x; j < UPAD; j += 256) {
        float v = 0.f;
        if (j < U_) {
            const float u1 = up[j], u2 = up[U_ + j];
            const float g =
                0.5f * u1 * (1.f + tanhf(0.7978845608028654f * (u1 + 0.044715f * u1 * u1 * u1)));
            v = g * u2;
        }
        split2(v, g_act_h[(size_t)bt * UPAD + j], g_act_l[(size_t)bt * UPAD + j]);
    }
}

extern "C" void kernel_launch(void* const* d_in, const int* in_sizes, int n_in,
                              void* d_out, int out_size) {
    const float* x      = (const float*)d_in[0];
    const float* ln_w   = (const float*)d_in[1];
    const float* ln_b   = (const float*)d_in[2];
    const float* conv_w = (const float*)d_in[3];
    const float* conv_b = (const float*)d_in[4];
    const float* w_if   = (const float*)d_in[5];
    const float* w_zo   = (const float*)d_in[6];
    const float* w_hh   = (const float*)d_in[7];
    const float* bias   = (const float*)d_in[8];
    const float* gn_w   = (const float*)d_in[9];
    const float* gn_b   = (const float*)d_in[10];
    const float* up_w   = (const float*)d_in[11];
    const float* up_b   = (const float*)d_in[12];
    const float* down_w = (const float*)d_in[13];
    const float* down_b = (const float*)d_in[14];
    float* out = (float*)d_out;

    static const int SMEM = TILES0 + 2 * STG_BYTES;
    static const int SMEMR = (32768 + 1024 + 256 + 16) * 4;
    cudaFuncSetAttribute(gemm_tc, cudaFuncAttributeMaxDynamicSharedMemorySize, SMEM);
    cudaFuncSetAttribute(recurrence_cluster, cudaFuncAttributeMaxDynamicSharedMemorySize, SMEMR);

    float *p_iflin, *p_zolin, *p_up, *p_upb;
    cudaGetSymbolAddress((void**)&p_iflin, g_iflin);
    cudaGetSymbolAddress((void**)&p_zolin, g_zolin);
    cudaGetSymbolAddress((void**)&p_up, g_up);
    cudaGetSymbolAddress((void**)&p_upb, g_upb);
    __nv_bfloat16 *xnh, *xnl, *ifh, *ifl, *znh, *znl, *ach, *acl;
    __nv_bfloat16 *wifh, *wifl, *wzoh, *wzol, *wuph, *wupl, *wdnh, *wdnl;
    cudaGetSymbolAddress((void**)&xnh, g_xn_h);   cudaGetSymbolAddress((void**)&xnl, g_xn_l);
    cudaGetSymbolAddress((void**)&ifh, g_if_h);   cudaGetSymbolAddress((void**)&ifl, g_if_l);
    cudaGetSymbolAddress((void**)&znh, g_zn_h);   cudaGetSymbolAddress((void**)&znl, g_zn_l);
    cudaGetSymbolAddress((void**)&ach, g_act_h);  cudaGetSymbolAddress((void**)&acl, g_act_l);
    cudaGetSymbolAddress((void**)&wifh, g_wif_h); cudaGetSymbolAddress((void**)&wifl, g_wif_l);
    cudaGetSymbolAddress((void**)&wzoh, g_wzo_h); cudaGetSymbolAddress((void**)&wzol, g_wzo_l);
    cudaGetSymbolAddress((void**)&wuph, g_wup_h); cudaGetSymbolAddress((void**)&wupl, g_wup_l);
    cudaGetSymbolAddress((void**)&wdnh, g_wdn_h); cudaGetSymbolAddress((void**)&wdnl, g_wdn_l);

    // launch 0..2
    ln_kernel<<<BT_, 256>>>(x, ln_w, ln_b);
    conv_swish_kernel<<<BT_, 256>>>(conv_w, conv_b);
    split_kernel<<<2048, 256>>>(w_if, wifh, wifl, 2048 * 1024);
    // launch 3 = ncu target
    gemm_tc<<<dim3(8, 128), 128, SMEM>>>(ifh, ifl, 1024, wifh, wifl, 1024,
                                         p_iflin, 2048, 1024, nullptr, nullptr);
    split_kernel<<<2048, 256>>>(w_zo, wzoh, wzol, 2048 * 1024);
    gemm_tc<<<dim3(8, 128), 128, SMEM>>>(xnh, xnl, 1024, wzoh, wzol, 1024,
                                         p_zolin, 2048, 1024, nullptr, nullptr);
    transpose_whh<<<dim3(32, 8, 4), dim3(32, 8)>>>(w_hh);
    recurrence_cluster<<<128, 128, SMEMR>>>(bias, gn_w, gn_b);
    pad_split_upw<<<U2P, 256>>>(up_w);
    pad_upb_kernel<<<(U2P + 255) / 256, 256>>>(up_b);
    gemm_tc<<<dim3(11, 128), 128, SMEM>>>(znh, znl, 1024, wuph, wupl, 1024,
                                          p_up, U2P, 1024, p_upb, nullptr);
    glu_kernel<<<BT_, 256>>>();
    pad_split_downw<<<1024, 256>>>(down_w);
    gemm_tc<<<dim3(4, 128), 128, SMEM>>>(ach, acl, UPAD, wdnh, wdnl, UPAD,
                                         out, 1024, UPAD, down_b, x);
}

// round 12
// speedup vs baseline: 1.4591x; 1.4591x over previous
#include <cuda_runtime.h>
#include <cuda_bf16.h>
#include <cstdint>
#include <cstddef>

#define B_   8
#define T_   2048
#define D_   1024
#define H_   4
#define HS_  256
#define U_   1365
#define U2_  2730
#define U2P  2816
#define UPAD 1408
#define BT_  (B_ * T_)
#define EPSV 1e-5f

#if defined(__CUDA_ARCH_FEAT_SM103_ALL) || defined(__CUDA_ARCH_FEAT_SM100_ALL)
#define HAS_TC 1
#else
#define HAS_TC 0
#endif

// ---------------- scratch ----------------
__device__ float g_xn[(size_t)BT_ * D_];
__device__ float g_iflin[(size_t)BT_ * 2048];
__device__ float g_zolin[(size_t)BT_ * 2048];
__device__ float g_up[(size_t)BT_ * U2P];
__device__ float g_whhT[H_ * HS_ * 1024];
__device__ float g_upb[U2P];

__device__ __nv_bfloat16 g_xn_h[(size_t)BT_ * D_];
__device__ __nv_bfloat16 g_xn_l[(size_t)BT_ * D_];
__device__ __nv_bfloat16 g_if_h[(size_t)BT_ * D_];
__device__ __nv_bfloat16 g_if_l[(size_t)BT_ * D_];
__device__ __nv_bfloat16 g_zn_h[(size_t)BT_ * D_];
__device__ __nv_bfloat16 g_zn_l[(size_t)BT_ * D_];
__device__ __nv_bfloat16 g_act_h[(size_t)BT_ * UPAD];
__device__ __nv_bfloat16 g_act_l[(size_t)BT_ * UPAD];
__device__ __nv_bfloat16 g_wif_h[2048 * 1024];
__device__ __nv_bfloat16 g_wif_l[2048 * 1024];
__device__ __nv_bfloat16 g_wzo_h[2048 * 1024];
__device__ __nv_bfloat16 g_wzo_l[2048 * 1024];
__device__ __nv_bfloat16 g_wup_h[(size_t)U2P * 1024];
__device__ __nv_bfloat16 g_wup_l[(size_t)U2P * 1024];
__device__ __nv_bfloat16 g_wdn_h[1024 * UPAD];
__device__ __nv_bfloat16 g_wdn_l[1024 * UPAD];

__device__ __forceinline__ void split2(float v, __nv_bfloat16& h, __nv_bfloat16& l) {
    h = __float2bfloat16(v);
    l = __float2bfloat16(v - __bfloat162float(h));
}

// ============ launch 0: mega-prep (LN + all weight splits + transpose) ============
#define LN_END    16384
#define SIF_END   (LN_END + 2048)
#define SZO_END   (SIF_END + 2048)
#define UPW_END   (SZO_END + U2P)
#define DNW_END   (UPW_END + 1024)
#define TRN_END   (DNW_END + 1024)
#define PREP_GRID (TRN_END + 11)

__global__ void __launch_bounds__(256) megaprep_ln(
    const float* __restrict__ x, const float* __restrict__ ln_w,
    const float* __restrict__ ln_b, const float* __restrict__ w_if,
    const float* __restrict__ w_zo, const float* __restrict__ up_w,
    const float* __restrict__ dw, const float* __restrict__ whh,
    const float* __restrict__ up_b) {
    __shared__ float sred[18];
    __shared__ float tile[32][33];
    const int bid = blockIdx.x, tid = threadIdx.x;

    if (bid < LN_END) {
        const int bt = bid;
        const float4 xv = reinterpret_cast<const float4*>(x + (size_t)bt * D_)[tid];
        float s = xv.x + xv.y + xv.z + xv.w;
        float q = xv.x * xv.x + xv.y * xv.y + xv.z * xv.z + xv.w * xv.w;
#pragma unroll
        for (int off = 16; off; off >>= 1) {
            s += __shfl_xor_sync(0xffffffffu, s, off);
            q += __shfl_xor_sync(0xffffffffu, q, off);
        }
        if ((tid & 31) == 0) { sred[tid >> 5] = s; sred[8 + (tid >> 5)] = q; }
        __syncthreads();
        if (tid == 0) {
            float ts = 0.f, tq = 0.f;
#pragma unroll
            for (int i = 0; i < 8; i++) { ts += sred[i]; tq += sred[8 + i]; }
            sred[16] = ts; sred[17] = tq;
        }
        __syncthreads();
        const float mean = sred[16] * (1.f / D_);
        const float var  = sred[17] * (1.f / D_) - mean * mean;
        const float inv  = rsqrtf(var + EPSV);
        const float4 wv = reinterpret_cast<const float4*>(ln_w)[tid];
        const float4 bv = reinterpret_cast<const float4*>(ln_b)[tid];
        float4 r;
        r.x = (xv.x - mean) * inv * wv.x + bv.x;
        r.y = (xv.y - mean) * inv * wv.y + bv.y;
        r.z = (xv.z - mean) * inv * wv.z + bv.z;
        r.w = (xv.w - mean) * inv * wv.w + bv.w;
        reinterpret_cast<float4*>(g_xn + (size_t)bt * D_)[tid] = r;
        const size_t o = (size_t)bt * D_ + tid * 4;
        split2(r.x, g_xn_h[o + 0], g_xn_l[o + 0]);
        split2(r.y, g_xn_h[o + 1], g_xn_l[o + 1]);
        split2(r.z, g_xn_h[o + 2], g_xn_l[o + 2]);
        split2(r.w, g_xn_h[o + 3], g_xn_l[o + 3]);
    } else if (bid < SIF_END) {
        const size_t base = (size_t)(bid - LN_END) * 1024;
        for (int j = tid; j < 1024; j += 256)
            split2(w_if[base + j], g_wif_h[base + j], g_wif_l[base + j]);
    } else if (bid < SZO_END) {
        const size_t base = (size_t)(bid - SIF_END) * 1024;
        for (int j = tid; j < 1024; j += 256)
            split2(w_zo[base + j], g_wzo_h[base + j], g_wzo_l[base + j]);
    } else if (bid < UPW_END) {
        const int n = bid - SZO_END;
        for (int j = tid; j < 1024; j += 256) {
            float v = (n < U2_) ? up_w[(size_t)n * 1024 + j] : 0.f;
            split2(v, g_wup_h[(size_t)n * 1024 + j], g_wup_l[(size_t)n * 1024 + j]);
        }
    } else if (bid < DNW_END) {
        const int n = bid - UPW_END;
        for (int j = tid; j < UPAD; j += 256) {
            float v = (j < U_) ? dw[(size_t)n * U_ + j] : 0.f;
            split2(v, g_wdn_h[(size_t)n * UPAD + j], g_wdn_l[(size_t)n * UPAD + j]);
        }
    } else if (bid < TRN_END) {
        const int tb = bid - DNW_END;
        const int xo = tb & 31, yo = (tb >> 5) & 7, h = tb >> 8;
        const int o0 = xo * 32, s0 = yo * 32;
        const int tx = tid & 31, ty = tid >> 5;
        for (int i = ty; i < 32; i += 8)
            tile[i][tx] = whh[((size_t)h * 1024 + o0 + i) * 256 + s0 + tx];
        __syncthreads();
        for (int i = ty; i < 32; i += 8)
            g_whhT[((size_t)h * 256 + s0 + i) * 1024 + o0 + tx] = tile[tx][i];
    } else {
        const int i = (bid - TRN_END) * 256 + tid;
        if (i < U2P) g_upb[i] = (i < U2_) ? up_b[i] : 0.f;
    }
}

// ---------------- launch 1: causal conv K=4 + swish ----------------
__global__ void __launch_bounds__(256) conv_swish_kernel(const float* __restrict__ conv_w,
                                                         const float* __restrict__ conv_b) {
    const int bt = blockIdx.x;
    const int b = bt / T_, t = bt % T_;
    const int tid = threadIdx.x, c0 = tid * 4;
    float4 acc = reinterpret_cast<const float4*>(conv_b)[tid];
    const float4 w0 = reinterpret_cast<const float4*>(conv_w)[c0 + 0];
    const float4 w1 = reinterpret_cast<const float4*>(conv_w)[c0 + 1];
    const float4 w2 = reinterpret_cast<const float4*>(conv_w)[c0 + 2];
    const float4 w3 = reinterpret_cast<const float4*>(conv_w)[c0 + 3];
#pragma unroll
    for (int k = 0; k < 4; k++) {
        const int tt = t - 3 + k;
        if (tt >= 0) {
            const float4 xv =
                reinterpret_cast<const float4*>(g_xn + (size_t)(b * T_ + tt) * D_)[tid];
            acc.x += ((const float*)&w0)[k] * xv.x;
            acc.y += ((const float*)&w1)[k] * xv.y;
            acc.z += ((const float*)&w2)[k] * xv.z;
            acc.w += ((const float*)&w3)[k] * xv.w;
        }
    }
    const size_t o = (size_t)bt * D_ + c0;
    float vx = acc.x / (1.f + expf(-acc.x));
    float vy = acc.y / (1.f + expf(-acc.y));
    float vz = acc.z / (1.f + expf(-acc.z));
    float vw = acc.w / (1.f + expf(-acc.w));
    split2(vx, g_if_h[o + 0], g_if_l[o + 0]);
    split2(vy, g_if_h[o + 1], g_if_l[o + 1]);
    split2(vz, g_if_h[o + 2], g_if_l[o + 2]);
    split2(vw, g_if_h[o + 3], g_if_l[o + 3]);
}

// ================= tcgen05 GEMM (dual-capable via blockIdx.z) =================
#define STG_BYTES 98304
#define TILES0    1024
#define IDESC ((1u << 4) | (1u << 7) | (1u << 10) | (32u << 17) | (8u << 24))
#define DESC_BASE ((2ull << 61) | (1ull << 46) | (64ull << 32) | (1ull << 16))

#if HAS_TC
static __device__ __forceinline__ uint32_t sw128(uint32_t off) {
    return off ^ ((off >> 3) & 0x70);
}
static __device__ __forceinline__ void cpa16(uint32_t dst, const void* src) {
    asm volatile("cp.async.cg.shared.global [%0], [%1], 16;" :: "r"(dst), "l"(src));
}
static __device__ __forceinline__ void mma_f16_ss(uint32_t d, uint64_t a, uint64_t b,
                                                  uint32_t en) {
    asm volatile(
        "{\n\t.reg .pred p;\n\t"
        "setp.ne.u32 p, %5, 0;\n\t"
        "tcgen05.mma.cta_group::1.kind::f16 [%0], %1, %2, %3, {%4,%4,%4,%4}, p;\n\t}"
        :: "r"(d), "l"(a), "l"(b), "r"(IDESC), "r"(0u), "r"(en) : "memory");
}
static __device__ __forceinline__ void mwait(uint32_t mbar, uint32_t parity) {
    asm volatile(
        "{\n\t.reg .pred P;\n\t"
        "LW%=:\n\t"
        "mbarrier.try_wait.parity.shared.b64 P, [%0], %1;\n\t"
        "@!P bra LW%=;\n\t}"
        :: "r"(mbar), "r"(parity) : "memory");
}
static __device__ __forceinline__ void load_stage_tc(uint32_t sb, int s, int tid,
    const __nv_bfloat16* Ah, const __nv_bfloat16* Al, int lda, int m0,
    const __nv_bfloat16* Bh, const __nv_bfloat16* Bl, int ldb, int n0, int k0) {
    const uint32_t st = sb + TILES0 + s * STG_BYTES;
#pragma unroll
    for (int j = 0; j < 8; j++) {
        const int i = tid + j * 128;
        const int row = i >> 3, c16 = i & 7;
        const uint32_t sw = sw128(row * 128 + c16 * 16);
        const size_t go = (size_t)(m0 + row) * lda + k0 + c16 * 8;
        cpa16(st + sw,         Ah + go);
        cpa16(st + 16384 + sw, Al + go);
    }
#pragma unroll
    for (int j = 0; j < 16; j++) {
        const int i = tid + j * 128;
        const int row = i >> 3, c16 = i & 7;
        const uint32_t sw = sw128(row * 128 + c16 * 16);
        const size_t go = (size_t)(n0 + row) * ldb + k0 + c16 * 8;
        cpa16(st + 32768 + sw, Bh + go);
        cpa16(st + 65536 + sw, Bl + go);
    }
    asm volatile("cp.async.commit_group;");
}
#endif

__global__ void __launch_bounds__(128) gemm_tc(
    const __nv_bfloat16* Ah, const __nv_bfloat16* Al, int lda,
    const __nv_bfloat16* Bh, const __nv_bfloat16* Bl, int ldb,
    float* C, int ldc, int K,
    const float* bias, const float* res,
    const __nv_bfloat16* Ah2, const __nv_bfloat16* Al2,
    const __nv_bfloat16* Bh2, const __nv_bfloat16* Bl2, float* C2) {
#if HAS_TC
    if (blockIdx.z) { Ah = Ah2; Al = Al2; Bh = Bh2; Bl = Bl2; C = C2; }
    extern __shared__ char smem[];
    const uint32_t sb = (uint32_t)__cvta_generic_to_shared(smem);
    const int tid = threadIdx.x;
    const int m0 = blockIdx.y * 128, n0 = blockIdx.x * 256;
    const int iters = K >> 6;

    if (tid < 32) {
        asm volatile("tcgen05.alloc.cta_group::1.sync.aligned.shared::cta.b32 [%0], %1;"
                     :: "r"(sb), "r"(256u) : "memory");
        asm volatile("tcgen05.relinquish_alloc_permit.cta_group::1.sync.aligned;");
    }
    if (tid == 0) {
        asm volatile("mbarrier.init.shared.b64 [%0], 1;" :: "r"(sb + 8)  : "memory");
        asm volatile("mbarrier.init.shared.b64 [%0], 1;" :: "r"(sb + 16) : "memory");
    }
    __syncthreads();
    uint32_t tmem;
    asm volatile("ld.shared.b32 %0, [%1];" : "=r"(tmem) : "r"(sb));

    int pp[2] = {0, 0};
    load_stage_tc(sb, 0, tid, Ah, Al, lda, m0, Bh, Bl, ldb, n0, 0);

    for (int it = 0; it < iters; it++) {
        const int s = it & 1;
        if (it + 1 < iters) {
            const int o = s ^ 1;
            if (it >= 1) { mwait(sb + 8 + o * 8, pp[o]); pp[o] ^= 1; }
            load_stage_tc(sb, o, tid, Ah, Al, lda, m0, Bh, Bl, ldb, n0, (it + 1) * 64);
            asm volatile("cp.async.wait_group 1;");
        } else {
            asm volatile("cp.async.wait_group 0;");
        }
        asm volatile("fence.proxy.async.shared::cta;" ::: "memory");
        __syncthreads();
        if (tid == 0) {
            const uint32_t st = sb + TILES0 + s * STG_BYTES;
            const uint64_t ah = DESC_BASE | ((uint64_t)(st >> 4) & 0x3FFF);
            const uint64_t al = DESC_BASE | ((uint64_t)((st + 16384) >> 4) & 0x3FFF);
            const uint64_t bh = DESC_BASE | ((uint64_t)((st + 32768) >> 4) & 0x3FFF);
            const uint64_t bl = DESC_BASE | ((uint64_t)((st + 65536) >> 4) & 0x3FFF);
#pragma unroll
            for (int ks = 0; ks < 4; ks++) {
                mma_f16_ss(tmem, ah + ks * 2, bh + ks * 2, (it > 0 || ks > 0) ? 1u : 0u);
                mma_f16_ss(tmem, ah + ks * 2, bl + ks * 2, 1u);
                mma_f16_ss(tmem, al + ks * 2, bh + ks * 2, 1u);
            }
            asm volatile(
                "tcgen05.commit.cta_group::1.mbarrier::arrive::one.shared::cluster.b64 [%0];"
                :: "r"(sb + 8 + s * 8) : "memory");
        }
    }
    const int sl = (iters - 1) & 1;
    mwait(sb + 8 + sl * 8, pp[sl]);
    asm volatile("tcgen05.fence::after_thread_sync;" ::: "memory");
    __syncthreads();

    const int wid = tid >> 5, lid = tid & 31;
    const int row = m0 + wid * 32 + lid;
    float* crow = C + (size_t)row * ldc;
    const float* rrow = res ? res + (size_t)row * ldc : nullptr;
    for (int cb = 0; cb < 8; cb++) {
        uint32_t r[32];
        asm volatile(
            "tcgen05.ld.sync.aligned.32x32b.x32.b32 "
            "{%0,%1,%2,%3,%4,%5,%6,%7,%8,%9,%10,%11,%12,%13,%14,%15,"
            "%16,%17,%18,%19,%20,%21,%22,%23,%24,%25,%26,%27,%28,%29,%30,%31}, [%32];"
            : "=r"(r[0]), "=r"(r[1]), "=r"(r[2]), "=r"(r[3]), "=r"(r[4]), "=r"(r[5]),
              "=r"(r[6]), "=r"(r[7]), "=r"(r[8]), "=r"(r[9]), "=r"(r[10]), "=r"(r[11]),
              "=r"(r[12]), "=r"(r[13]), "=r"(r[14]), "=r"(r[15]), "=r"(r[16]), "=r"(r[17]),
              "=r"(r[18]), "=r"(r[19]), "=r"(r[20]), "=r"(r[21]), "=r"(r[22]), "=r"(r[23]),
              "=r"(r[24]), "=r"(r[25]), "=r"(r[26]), "=r"(r[27]), "=r"(r[28]), "=r"(r[29]),
              "=r"(r[30]), "=r"(r[31])
            : "r"(tmem + cb * 32));
        asm volatile("tcgen05.wait::ld.sync.aligned;" ::: "memory");
        const int c0 = n0 + cb * 32;
#pragma unroll
        for (int j = 0; j < 32; j += 4) {
            float4 v = make_float4(__uint_as_float(r[j]), __uint_as_float(r[j + 1]),
                                   __uint_as_float(r[j + 2]), __uint_as_float(r[j + 3]));
            if (bias) {
                v.x += bias[c0 + j];     v.y += bias[c0 + j + 1];
                v.z += bias[c0 + j + 2]; v.w += bias[c0 + j + 3];
            }
            if (rrow) {
                v.x += rrow[c0 + j];     v.y += rrow[c0 + j + 1];
                v.z += rrow[c0 + j + 2]; v.w += rrow[c0 + j + 3];
            }
            *reinterpret_cast<float4*>(crow + c0 + j) = v;
        }
    }
    __syncthreads();
    if (tid < 32)
        asm volatile("tcgen05.dealloc.cta_group::1.sync.aligned.b32 %0, %1;"
                     :: "r"(tmem), "r"(256u));
#endif
}

// ============ recurrence v3: 8-CTA cluster, 256 threads, f32x2 matvec ============
static __device__ __forceinline__ uint32_t smem_u32(const void* p) {
    return (uint32_t)__cvta_generic_to_shared(p);
}
static __device__ __forceinline__ void dsmem_st_f32(uint32_t laddr, uint32_t rank, float v) {
    uint32_t ra;
    asm volatile("mapa.shared::cluster.u32 %0, %1, %2;" : "=r"(ra) : "r"(laddr), "r"(rank));
    asm volatile("st.shared::cluster.b32 [%0], %1;" :: "r"(ra), "r"(__float_as_uint(v)));
}
static __device__ __forceinline__ void csync() {
    asm volatile("barrier.cluster.arrive.aligned;" ::: "memory");
    asm volatile("barrier.cluster.wait.aligned;" ::: "memory");
}

#define WPITCH 260

__global__ void __launch_bounds__(256) __cluster_dims__(8, 1, 1)
recurrence_cluster(const float* __restrict__ bias,
                   const float* __restrict__ gn_w,
                   const float* __restrict__ gn_b) {
    extern __shared__ float sm[];
    float* sW   = sm;                     // [128][WPITCH]
    float* sH   = sm + 128 * WPITCH;      // [2][2][256] (buf, batch, s)
    float* sPre = sH + 1024;              // [2][128]
    float* sRed = sPre + 256;             // 16

    const int tid = threadIdx.x;
    uint32_t rank;
    asm("mov.u32 %0, %%cluster_ctarank;" : "=r"(rank));
    const int cid = blockIdx.x >> 3;
    const int h = cid & 3, bp = cid >> 2;
    const int b0 = bp * 2;
    const int o = tid & 127, b = tid >> 7;
    const int g = o >> 5, sl = o & 31;
    const int orow = g * 256 + (int)rank * 32 + sl;

    // weights: sW[o][s] = whhT[h][s][orow(o)]  (coalesced gmem reads over o)
    for (int i = tid; i < 32768; i += 256) {
        const int s = i >> 7, oo = i & 127;
        const int gg = oo >> 5, ss = oo & 31;
        sW[oo * WPITCH + s] =
            g_whhT[((size_t)(h * 256 + s)) * 1024 + gg * 256 + (int)rank * 32 + ss];
    }
    for (int i = tid; i < 1024; i += 256) sH[i] = 0.f;

    const float bia = bias[h * 1024 + orow];
    const float* linp; int lcol;
    if (g < 2) { linp = g_iflin; lcol = h * 512 + g * 256 + (int)rank * 32 + sl; }
    else       { linp = g_zolin; lcol = h * 512 + (g - 2) * 256 + (int)rank * 32 + sl; }
    const int bb = b0 + b;
    const int s_out = (int)rank * 32 + (tid & 31);
    const float gwv = gn_w[h * 256 + s_out];
    const float gbv = gn_b[h * 256 + s_out];

    float cS = 0.f, nS = 0.f, mS = 0.f;
    __syncthreads();
    csync();

    const uint32_t sH_a = smem_u32(sH);
    const float* wrow = sW + o * WPITCH;

    for (int t = 0; t < T_; t++) {
        const int cur = t & 1, nxt = cur ^ 1;
        const float lp = linp[(size_t)(bb * T_ + t) * 2048 + lcol];
        const float* hrow = sH + cur * 512 + b * 256;
        float acc;
#if HAS_TC
        {
            unsigned long long a01 = 0ull, a23 = 0ull;
            const double2* wv = reinterpret_cast<const double2*>(wrow);
            const double2* hv = reinterpret_cast<const double2*>(hrow);
#pragma unroll
            for (int s4 = 0; s4 < 64; s4++) {
                const double2 w = wv[s4];
                const double2 hh = hv[s4];
                asm("fma.rn.f32x2 %0, %1, %2, %0;"
                    : "+l"(a01) : "l"(__double_as_longlong(w.x)), "l"(__double_as_longlong(hh.x)));
                asm("fma.rn.f32x2 %0, %1, %2, %0;"
                    : "+l"(a23) : "l"(__double_as_longlong(w.y)), "l"(__double_as_longlong(hh.y)));
            }
            float l0, h0, l1, h1;
            asm("mov.b64 {%0,%1}, %2;" : "=f"(l0), "=f"(h0) : "l"(a01));
            asm("mov.b64 {%0,%1}, %2;" : "=f"(l1), "=f"(h1) : "l"(a23));
            acc = (l0 + h0) + (l1 + h1);
        }
#else
        {
            float A0 = 0.f, A1 = 0.f, A2 = 0.f, A3 = 0.f;
#pragma unroll
            for (int s4 = 0; s4 < 64; s4++) {
                const float4 w = reinterpret_cast<const float4*>(wrow)[s4];
                const float4 hh = reinterpret_cast<const float4*>(hrow)[s4];
                A0 += w.x * hh.x; A1 += w.y * hh.y; A2 += w.z * hh.z; A3 += w.w * hh.w;
            }
            acc = (A0 + A1) + (A2 + A3);
        }
#endif
        sPre[b * 128 + o] = acc + lp + bia;
        __syncthreads();

        if (tid < 64) {
            const int bsel = tid >> 5, lane = tid & 31;
            const float* pr = sPre + bsel * 128;
            const float iv = pr[lane];
            const float fv = pr[32 + lane];
            const float zv = tanhf(pr[64 + lane]);
            const float og = 1.f / (1.f + expf(-pr[96 + lane]));
            const float mn = fmaxf(fv + mS, iv);
            const float ie = expf(iv - mn);
            const float fe = expf(fv + mS - mn);
            cS = fe * cS + ie * zv;
            nS = fe * nS + ie;
            mS = mn;
            const float hv = og * (cS / nS);
            const uint32_t la = sH_a + (nxt * 512 + bsel * 256 + s_out) * 4;
#pragma unroll
            for (int p = 0; p < 8; p++) dsmem_st_f32(la, (uint32_t)p, hv);
        }
        csync();

        // GroupNorm stats: each thread reduces 2 values of its batch
        const float* hn = sH + nxt * 512 + b * 256;
        const float x0 = hn[o], x1 = hn[128 + o];
        float s_ = x0 + x1, q_ = x0 * x0 + x1 * x1;
#pragma unroll
        for (int off = 16; off; off >>= 1) {
            s_ += __shfl_xor_sync(0xffffffffu, s_, off);
            q_ += __shfl_xor_sync(0xffffffffu, q_, off);
        }
        if ((tid & 31) == 0) {
            const int w = tid >> 5;
            sRed[w] = s_; sRed[8 + w] = q_;
        }
        __syncthreads();
        if (tid < 64) {
            const int bsel = tid >> 5;
            const float ts = sRed[bsel * 4] + sRed[bsel * 4 + 1] +
                             sRed[bsel * 4 + 2] + sRed[bsel * 4 + 3];
            const float tq = sRed[8 + bsel * 4] + sRed[8 + bsel * 4 + 1] +
                             sRed[8 + bsel * 4 + 2] + sRed[8 + bsel * 4 + 3];
            const float mu  = ts * (1.f / 256.f);
            const float var = tq * (1.f / 256.f) - mu * mu;
            const float inv = rsqrtf(var + EPSV);
            const float hval = sH[nxt * 512 + bsel * 256 + s_out];
            const float zn = (hval - mu) * inv * gwv + gbv;
            const size_t zo = (size_t)((b0 + bsel) * T_ + t) * D_ + h * 256 + s_out;
            split2(zn, g_zn_h[zo], g_zn_l[zo]);
        }
        __syncthreads();
    }
}

// ---------------- GLU ----------------
__global__ void __launch_bounds__(256) glu_kernel() {
    const int bt = blockIdx.x;
    const float* up = g_up + (size_t)bt * U2P;
    for (int j = threadIdx.x; j < UPAD; j += 256) {
        float v = 0.f;
        if (j < U_) {
            const float u1 = up[j], u2 = up[U_ + j];
            const float g =
                0.5f * u1 * (1.f + tanhf(0.7978845608028654f * (u1 + 0.044715f * u1 * u1 * u1)));
            v = g * u2;
        }
        split2(v, g_act_h[(size_t)bt * UPAD + j], g_act_l[(size_t)bt * UPAD + j]);
    }
}

extern "C" void kernel_launch(void* const* d_in, const int* in_sizes, int n_in,
                              void* d_out, int out_size) {
    const float* x      = (const float*)d_in[0];
    const float* ln_w   = (const float*)d_in[1];
    const float* ln_b   = (const float*)d_in[2];
    const float* conv_w = (const float*)d_in[3];
    const float* conv_b = (const float*)d_in[4];
    const float* w_if   = (const float*)d_in[5];
    const float* w_zo   = (const float*)d_in[6];
    const float* w_hh   = (const float*)d_in[7];
    const float* bias   = (const float*)d_in[8];
    const float* gn_w   = (const float*)d_in[9];
    const float* gn_b   = (const float*)d_in[10];
    const float* up_w   = (const float*)d_in[11];
    const float* up_b   = (const float*)d_in[12];
    const float* down_w = (const float*)d_in[13];
    const float* down_b = (const float*)d_in[14];
    float* out = (float*)d_out;

    static const int SMEM  = TILES0 + 2 * STG_BYTES;
    static const int SMEMR = (128 * WPITCH + 1024 + 256 + 16) * 4;   // 138304
    cudaFuncSetAttribute(gemm_tc, cudaFuncAttributeMaxDynamicSharedMemorySize, SMEM);
    cudaFuncSetAttribute(recurrence_cluster, cudaFuncAttributeMaxDynamicSharedMemorySize, SMEMR);

    float *p_iflin, *p_zolin, *p_up, *p_upb;
    cudaGetSymbolAddress((void**)&p_iflin, g_iflin);
    cudaGetSymbolAddress((void**)&p_zolin, g_zolin);
    cudaGetSymbolAddress((void**)&p_up, g_up);
    cudaGetSymbolAddress((void**)&p_upb, g_upb);
    __nv_bfloat16 *xnh, *xnl, *ifh, *ifl, *znh, *znl, *ach, *acl;
    __nv_bfloat16 *wifh, *wifl, *wzoh, *wzol, *wuph, *wupl, *wdnh, *wdnl;
    cudaGetSymbolAddress((void**)&xnh, g_xn_h);   cudaGetSymbolAddress((void**)&xnl, g_xn_l);
    cudaGetSymbolAddress((void**)&ifh, g_if_h);   cudaGetSymbolAddress((void**)&ifl, g_if_l);
    cudaGetSymbolAddress((void**)&znh, g_zn_h);   cudaGetSymbolAddress((void**)&znl, g_zn_l);
    cudaGetSymbolAddress((void**)&ach, g_act_h);  cudaGetSymbolAddress((void**)&acl, g_act_l);
    cudaGetSymbolAddress((void**)&wifh, g_wif_h); cudaGetSymbolAddress((void**)&wifl, g_wif_l);
    cudaGetSymbolAddress((void**)&wzoh, g_wzo_h); cudaGetSymbolAddress((void**)&wzol, g_wzo_l);
    cudaGetSymbolAddress((void**)&wuph, g_wup_h); cudaGetSymbolAddress((void**)&wupl, g_wup_l);
    cudaGetSymbolAddress((void**)&wdnh, g_wdn_h); cudaGetSymbolAddress((void**)&wdnl, g_wdn_l);

    // launch 0: all prep + LN
    megaprep_ln<<<PREP_GRID, 256>>>(x, ln_w, ln_b, w_if, w_zo, up_w, down_w, w_hh, up_b);
    // launch 1: conv + swish
    conv_swish_kernel<<<BT_, 256>>>(conv_w, conv_b);
    // launch 2: both projection GEMMs (z=0: if, z=1: zo)
    gemm_tc<<<dim3(8, 128, 2), 128, SMEM>>>(ifh, ifl, 1024, wifh, wifl, 1024,
                                            p_iflin, 2048, 1024, nullptr, nullptr,
                                            xnh, xnl, wzoh, wzol, p_zolin);
    // launch 3: recurrence  <-- ncu target
    recurrence_cluster<<<128, 256, SMEMR>>>(bias, gn_w, gn_b);
    // launch 4: up GEMM
    gemm_tc<<<dim3(11, 128, 1), 128, SMEM>>>(znh, znl, 1024, wuph, wupl, 1024,
                                             p_up, U2P, 1024, p_upb, nullptr,
                                             znh, znl, wuph, wupl, p_up);
    // launch 5: GLU
    glu_kernel<<<BT_, 256>>>();
    // launch 6: down GEMM (+bias +residual)
    gemm_tc<<<dim3(4, 128, 1), 128, SMEM>>>(ach, acl, UPAD, wdnh, wdnl, UPAD,
                                            out, 1024, UPAD, down_b, x,
                                            ach, acl, wdnh, wdnl, out);
}